// round 15
// baseline (speedup 1.0000x reference)
#include <cuda_runtime.h>
#include <math.h>
#include <float.h>

// WaveNet autoregressive generation, sm_103a — round 14 (= R13 + rpop fix).
// 128 CTAs x 1 row; warp-specialized: 256 main threads (conv/gate/res),
// 256 skip threads (lagged skip matmul, k-split 4). Gate and x-combine are
// pair-split across 4 warps via shfl_xor(1) (bit-identical tree halves).
// FIX vs R13: all dilation-queue pops (rpop) are loaded by tid<128 indexed
// by cc=tid>>1, matching the pair-split consumers in Phase D / step head.

#define NLAYER 30
#define BB 128
#define VV 256
#define RING_PER_ROW 3069   // 3 * (2^10 - 1) slots, 64 floats each

__device__ float g_ring[(size_t)BB * RING_PER_ROW * 64];  // ~100.6 MB scratch

#define BAR_MAIN() asm volatile("bar.sync 1, 256;" ::: "memory")

template<int N>
__device__ __forceinline__ void wload(float4* dst, const float4* __restrict__ Wg,
                                      int s4) {
#pragma unroll
    for (int u = 0; u < N; u++) dst[u] = Wg[(size_t)u * s4];
}

// FMA N k-steps (N%4==0), one row, weights from a register buffer.
template<int N>
__device__ __forceinline__ void mm_reg(const float* __restrict__ a0,
                                       const float4* w, float4& o0) {
#pragma unroll
    for (int c2 = 0; c2 < N; c2 += 4) {
        float v0[4];
        *(float4*)v0 = *(const float4*)(a0 + c2);
#pragma unroll
        for (int u = 0; u < 4; u++) {
            const float4 wv = w[c2 + u];
            o0.x = fmaf(v0[u], wv.x, o0.x);
            o0.y = fmaf(v0[u], wv.y, o0.y);
            o0.z = fmaf(v0[u], wv.z, o0.z);
            o0.w = fmaf(v0[u], wv.w, o0.w);
        }
    }
}

// FMA N k-steps streaming weights from global (independent LDGs pipeline).
template<int N>
__device__ __forceinline__ void mm_gl(const float* __restrict__ a0,
                                      const float4* __restrict__ Wg, int s4,
                                      float4& o0) {
#pragma unroll
    for (int c2 = 0; c2 < N; c2 += 4) {
        float v0[4];
        *(float4*)v0 = *(const float4*)(a0 + c2);
#pragma unroll
        for (int u = 0; u < 4; u++) {
            const float4 wv = Wg[(size_t)(c2 + u) * s4];
            o0.x = fmaf(v0[u], wv.x, o0.x);
            o0.y = fmaf(v0[u], wv.y, o0.y);
            o0.z = fmaf(v0[u], wv.z, o0.z);
            o0.w = fmaf(v0[u], wv.w, o0.w);
        }
    }
}

__global__ __launch_bounds__(512, 1)
void wavenet_kernel(const int* __restrict__ seed,
                    const float* __restrict__ emb,     // (V, 64)
                    const float* __restrict__ kern,    // (L, 2, 64, 128)
                    const float* __restrict__ cbias,   // (L, 128)
                    const float* __restrict__ rw,      // (L, 64, 64)
                    const float* __restrict__ rb,      // (L, 64)
                    const float* __restrict__ sw,      // (L, 64, 256)
                    const float* __restrict__ sb,      // (L, 256)
                    const float* __restrict__ ow0,     // (256, 256)
                    const float* __restrict__ ob0,     // (256)
                    const float* __restrict__ ow1,     // (256, 256)
                    const float* __restrict__ ob1,     // (256)
                    float* __restrict__ out,
                    int T, long long samp_off, long long logit_off, int mode)
{
    __shared__ __align__(16) float sx[64];
    __shared__ __align__(16) float sxl[64];
    __shared__ __align__(16) float sgb[2][64];          // double-buffered gate
    __shared__ __align__(16) float ssk[256];
    __shared__ __align__(16) float sh0[256];
    __shared__ __align__(16) float slg[256];
    __shared__ __align__(16) float cbs[NLAYER * 128];   // staged conv bias
    __shared__ __align__(16) float ssb[256];            // sum of skip biases
    __shared__ __align__(16) float obs0[256], obs1[256];
    __shared__ __align__(16) float pbuf[2048];          // 8KB partials union
    __shared__ int snidx;

    float (*scp)[128] = (float(*)[128])pbuf;   // [8][128] conv
    float (*srp)[64]  = (float(*)[64])pbuf;    // [16][64] res
    float (*ssp)[256] = (float(*)[256])pbuf;   // [8][256] skip/head

    const int tid = threadIdx.x;
    const int row = blockIdx.x;
    const bool is_main = tid < 256;

    // main mappings
    const int jqc = tid & 31, ksc = tid >> 5, kbc = ksc * 8;   // conv 32jq x 8ks
    const int jqr = tid & 15, ksr = tid >> 4, kbr = ksr * 4;   // res  16jq x 16ks
    const int c = tid;                                         // tid<64 scalar
    const int ch = tid;                                        // tid<256 combines
    const int pr = tid & 1, cc = tid >> 1;                     // tid<128 pair-split
    // head mapping over ALL 512 threads: 64jq x 8ks of 32
    const int jqh = tid & 63, ksh = tid >> 6, khb = ksh * 32;
    // skip-group mapping (tid >= 256, 256 threads): 64jq x 4ks of 16
    const int st = tid & 255;
    const int jqs = st & 63, kss = st >> 6, kbs = kss * 16;

    float4 wk[8];   // main: conv K0[0..3]|K1[4..7]; all: head rows khb..khb+7
    float4 wr[4];   // main: res prefetch
    float4 osk = {0, 0, 0, 0};  // skip-group accumulator
    float  rpop = 0.f, rbv = 0.f;

    // ---- one-time staging ----
    for (int idx = tid; idx < NLAYER * 128; idx += 512) cbs[idx] = cbias[idx];
    if (tid < 256) {
        float s = 0.f;
#pragma unroll 1
        for (int i = 0; i < NLAYER; i++) s += sb[i * 256 + tid];
        ssb[tid] = s;
        obs0[tid] = ob0[tid];
        obs1[tid] = ob1[tid];
    }
    if (tid == 0) snidx = seed[row];
    if (is_main) {   // prefetch conv (t=0, layer 0)
        wload<4>(wk,     (const float4*)kern + (size_t)kbc * 32 + jqc,        32);
        wload<4>(wk + 4, (const float4*)kern + (size_t)(64 + kbc) * 32 + jqc, 32);
    }
    __syncthreads();

#pragma unroll 1
    for (int t = 0; t < T; t++) {
        // ---- step head: emb by tid<64; sxl by even lanes of tid<128 (rpop
        //      was loaded cc-indexed by tid<128 at end of previous step) ----
        if (tid < 64) sx[c] = emb[(size_t)snidx * 64 + c];
        if (tid < 128 && pr == 0) sxl[cc] = rpop;
        if (!is_main) { osk.x = osk.y = osk.z = osk.w = 0.f; }

#pragma unroll 1
        for (int i = 0; i < NLAYER; i++) {
            __syncthreads();   // P_i: sx_i ready; sg[i-1] ready; skip_{i-2} done

            if (is_main) {
                const int d = 1 << (i % 10);
                const long long off = (long long)(i / 10) * 1023 + (d - 1);

                // -- A: conv partials (4 pre + 4 stream per matrix) + push + rb + wr
                {
                    const float4* K0 = (const float4*)kern
                        + (size_t)(i * 2) * 64 * 32 + (size_t)kbc * 32 + jqc;
                    const float4* K1 = K0 + 64 * 32;
                    float4 o0 = {0, 0, 0, 0};
                    mm_reg<4>(sxl + kbc,     wk,          o0);
                    mm_gl<4> (sxl + kbc + 4, K0 + 4 * 32, 32, o0);
                    mm_reg<4>(sx + kbc,      wk + 4,      o0);
                    mm_gl<4> (sx + kbc + 4,  K1 + 4 * 32, 32, o0);
                    *(float4*)&scp[ksc][4 * jqc] = o0;
                }
                if (tid < 64) {
                    size_t idx = ((size_t)row * RING_PER_ROW + (size_t)off
                                  + (t & (d - 1))) * 64 + c;
                    g_ring[idx] = sx[c];
                }
                if (tid < 128) rbv = rb[i * 64 + cc];   // even lanes use in D
                wload<4>(wr, (const float4*)rw + (size_t)i * 64 * 16
                             + (size_t)kbr * 16 + jqr, 16);
                BAR_MAIN();

                // -- B: gate (pair-split, 4 warps) + next conv prefetch + pop
                if (i < NLAYER - 1) {
                    const float4* KN = (const float4*)kern
                        + (size_t)((i + 1) * 2) * 64 * 32;
                    wload<4>(wk,     KN + (size_t)kbc * 32 + jqc,        32);
                    wload<4>(wk + 4, KN + (size_t)(64 + kbc) * 32 + jqc, 32);
                    if (tid < 128) {   // cc-indexed: pairs load the same word
                        const int d2 = 1 << ((i + 1) % 10);
                        const long long off2 = (long long)((i + 1) / 10) * 1023 + (d2 - 1);
                        size_t idx2 = ((size_t)row * RING_PER_ROW + (size_t)off2
                                       + (t & (d2 - 1))) * 64 + cc;
                        rpop = (t >= d2) ? g_ring[idx2] : 0.f;
                    }
                }
                if (tid < 128) {
                    // lane pr=0 sums the tanh half (col cc), pr=1 the sigmoid
                    // half (col cc+64); identical tree order to R12.
                    int col = cc + (pr << 6);
                    float p0 = scp[0][col], p1 = scp[1][col];
                    float p2 = scp[2][col], p3 = scp[3][col];
                    float p4 = scp[4][col], p5 = scp[5][col];
                    float p6 = scp[6][col], p7 = scp[7][col];
                    float s = (((p0+p1)+(p2+p3)) + ((p4+p5)+(p6+p7)))
                            + cbs[i * 128 + col];
                    float o = __shfl_xor_sync(0xffffffffu, s, 1);
                    float ht = pr ? o : s;
                    float hs = pr ? s : o;
                    float e2 = __expf(2.f * ht);
                    float th = 1.f - __fdividef(2.f, e2 + 1.f);
                    float sig = __fdividef(1.f, 1.f + __expf(-hs));
                    if (pr == 0) sgb[i & 1][cc] = th * sig;
                }
                BAR_MAIN();

                // -- C: res partials (fully prefetched)
                {
                    float4 o0 = {0, 0, 0, 0};
                    mm_reg<4>(sgb[i & 1] + kbr, wr, o0);
                    *(float4*)&srp[ksr][4 * jqr] = o0;
                }
                BAR_MAIN();

                // -- D: x combine (pair-split tree halves, bit-identical)
                if (tid < 128) {
                    int b = pr << 3;   // 0 or 8
                    float a0 = srp[b+0][cc] + srp[b+1][cc];
                    float a1 = srp[b+2][cc] + srp[b+3][cc];
                    float a2 = srp[b+4][cc] + srp[b+5][cc];
                    float a3 = srp[b+6][cc] + srp[b+7][cc];
                    float h = (a0 + a1) + (a2 + a3);
                    float o = __shfl_xor_sync(0xffffffffu, h, 1);
                    if (pr == 0) {
                        float v = sx[cc] + rbv + (h + o);
                        sx[cc] = v;
                        if (i < NLAYER - 1) sxl[cc] = rpop;
                    }
                }
            } else {
                // ---- skip group (256 thr): skip matmul of layer i-1 ----
                if (i > 0) {
                    const float4* SW = (const float4*)sw
                        + ((size_t)(i - 1) * 64 + kbs) * 64 + jqs;
                    mm_gl<16>(sgb[(i - 1) & 1] + kbs, SW, 64, osk);
                }
            }
        }
        __syncthreads();   // P_30: layer 29 gate + combine done

        // ---- tail: skip_29 (skip group) while everyone prefetches head W0 ----
        wload<8>(wk, (const float4*)ow0 + (size_t)khb * 64 + jqh, 64);
        if (!is_main) {
            const float4* SW = (const float4*)sw
                + ((size_t)(NLAYER - 1) * 64 + kbs) * 64 + jqs;
            mm_gl<16>(sgb[(NLAYER - 1) & 1] + kbs, SW, 64, osk);
            *(float4*)&ssp[kss][4 * jqs] = osk;
        }
        __syncthreads();

        // ---- skip combine + Σbias + relu ----
        if (is_main) {
            float v0 = ssb[ch] + ((ssp[0][ch] + ssp[1][ch])
                                + (ssp[2][ch] + ssp[3][ch]));
            ssk[ch] = fmaxf(v0, 0.f);
        }
        __syncthreads();

        // ---- head m0: h0 = relu(skip @ ow0 + ob0); all 512 threads ----
        {
            const float4* W = (const float4*)ow0 + (size_t)khb * 64 + jqh;
            float4 o0 = {0, 0, 0, 0};
            mm_reg<8>(ssk + khb, wk, o0);
            mm_gl<24>(ssk + khb + 8, W + 8 * 64, 64, o0);
            wload<8>(wk, (const float4*)ow1 + (size_t)khb * 64 + jqh, 64);
            *(float4*)&ssp[ksh][4 * jqh] = o0;
        }
        __syncthreads();
        if (is_main) {
            float v0 = obs0[ch] + (((ssp[0][ch] + ssp[1][ch])
                                  + (ssp[2][ch] + ssp[3][ch]))
                                  + ((ssp[4][ch] + ssp[5][ch])
                                  + (ssp[6][ch] + ssp[7][ch])));
            sh0[ch] = fmaxf(v0, 0.f);
        }
        __syncthreads();

        // ---- head m1: logits = h0 @ ow1 + ob1; all 512 threads ----
        {
            const float4* W = (const float4*)ow1 + (size_t)khb * 64 + jqh;
            float4 o0 = {0, 0, 0, 0};
            mm_reg<8>(sh0 + khb, wk, o0);
            mm_gl<24>(sh0 + khb + 8, W + 8 * 64, 64, o0);
            // prefetch (t+1, layer 0) conv weights + layer-0 pop (cc-indexed)
            if (is_main) {
                wload<4>(wk,     (const float4*)kern + (size_t)kbc * 32 + jqc,        32);
                wload<4>(wk + 4, (const float4*)kern + (size_t)(64 + kbc) * 32 + jqc, 32);
            }
            if (tid < 128)
                rpop = g_ring[((size_t)row * RING_PER_ROW) * 64 + cc];
            *(float4*)&ssp[ksh][4 * jqh] = o0;
        }
        __syncthreads();
        if (is_main) {
            float v0 = obs1[ch] + (((ssp[0][ch] + ssp[1][ch])
                                  + (ssp[2][ch] + ssp[3][ch]))
                                  + ((ssp[4][ch] + ssp[5][ch])
                                  + (ssp[6][ch] + ssp[7][ch])));
            slg[ch] = v0;
            if (mode & 2)
                out[logit_off + ((size_t)row * T + t) * VV + ch] = v0;
        }
        __syncthreads();

        // ---- argmax (first-max tie rule, matches jnp.argmax) ----
        if (tid < 32) {
            float bv = -FLT_MAX;
            int bi = 0;
#pragma unroll
            for (int jj = 0; jj < 8; jj++) {
                int j = tid + jj * 32;
                float v = slg[j];
                if (v > bv) { bv = v; bi = j; }
            }
#pragma unroll
            for (int o2 = 16; o2 > 0; o2 >>= 1) {
                float ov = __shfl_down_sync(0xffffffffu, bv, o2);
                int   oi = __shfl_down_sync(0xffffffffu, bi, o2);
                if (ov > bv || (ov == bv && oi < bi)) { bv = ov; bi = oi; }
            }
            if (tid == 0) {
                snidx = bi;
                if (mode & 1) out[samp_off + (size_t)row * T + t] = (float)bi;
                if (mode & 4) ((int*)out)[(size_t)row * T + t] = bi;
            }
        }
        __syncthreads();
    }
}

extern "C" void kernel_launch(void* const* d_in, const int* in_sizes, int n_in,
                              void* d_out, int out_size) {
    const int*   seed  = (const int*)d_in[0];
    const float* emb   = (const float*)d_in[1];
    const float* kern  = (const float*)d_in[2];
    const float* cbias = (const float*)d_in[3];
    const float* rw    = (const float*)d_in[4];
    const float* rb    = (const float*)d_in[5];
    const float* sw    = (const float*)d_in[6];
    const float* sb    = (const float*)d_in[7];
    const float* ow0   = (const float*)d_in[8];
    const float* ob0   = (const float*)d_in[9];
    const float* ow1   = (const float*)d_in[10];
    const float* ob1   = (const float*)d_in[11];
    (void)in_sizes; (void)n_in;

    int T, mode;
    long long samp_off = 0, logit_off = 0;
    if (out_size % (BB * (VV + 1)) == 0) {
        T = out_size / (BB * (VV + 1));
        mode = 1 | 2;                       // float samples then logits
        samp_off = 0;
        logit_off = (long long)BB * T;
    } else if (out_size % (BB * VV) == 0) {
        T = out_size / (BB * VV);
        mode = 2;                           // logits only
        logit_off = 0;
    } else {
        T = out_size / BB;
        mode = 4;                           // int32 samples only
    }

    wavenet_kernel<<<BB, 512>>>(seed, emb, kern, cbias, rw, rb, sw, sb,
                                ow0, ob0, ow1, ob1,
                                (float*)d_out, T, samp_off, logit_off, mode);
}